// round 1
// baseline (speedup 1.0000x reference)
#include <cuda_runtime.h>
#include <cstdint>

// Problem: vanilla tanh RNN
//   h_t = tanh(x_t W_ih^T + b_ih + h_{t-1} W_hh^T + b_hh)
//   outputs: (h_T [1,B,H], all h_t flattened [B*T, H])
// B=4096, T=256, I=H=64.
//
// Fused persistent kernel: 128 blocks x 256 threads, each block owns 32 batch
// rows for all 256 steps. Per step: two [32x64]@[64x64] tf32 warp-MMA GEMMs.
// Weights live in registers as B-fragments for the whole kernel; h lives in
// shared memory; x(t+1) is prefetched from gmem during step t.

constexpr int Bsz = 4096;
constexpr int T   = 256;
constexpr int IN  = 64;
constexpr int H   = 64;
constexpr int NB  = 32;    // batch rows per block
constexpr int SSTR = 68;   // padded shared row stride (conflict-free frag LDS)
constexpr int NTHREADS = 256;

__device__ __forceinline__ uint32_t f2tf(float f) {
    uint32_t r;
    asm("cvt.rna.tf32.f32 %0, %1;" : "=r"(r) : "f"(f));
    return r;
}

__device__ __forceinline__ void mma8(float* c, const uint32_t* a, const uint32_t* b) {
    asm volatile(
        "mma.sync.aligned.m16n8k8.row.col.f32.tf32.tf32.f32 "
        "{%0,%1,%2,%3}, {%4,%5,%6,%7}, {%8,%9}, {%0,%1,%2,%3};"
        : "+f"(c[0]), "+f"(c[1]), "+f"(c[2]), "+f"(c[3])
        : "r"(a[0]), "r"(a[1]), "r"(a[2]), "r"(a[3]), "r"(b[0]), "r"(b[1]));
}

// Accurate-enough fast tanh: 1 - 2/(e^{2z}+1).
// __expf -> MUFU.EX2 (rel err ~2^-21); __fdividef(2, huge) -> 0 so saturation
// at +/-1 is exact. Near z=0 the cancellation is benign (abs err ~ulp(1)).
__device__ __forceinline__ float fast_tanh(float z) {
    float e = __expf(2.0f * z);
    return 1.0f - __fdividef(2.0f, e + 1.0f);
}

__global__ void __launch_bounds__(NTHREADS, 1)
rnn_fused(const float* __restrict__ x, const float* __restrict__ h0,
          const float* __restrict__ Wih, const float* __restrict__ Whh,
          const float* __restrict__ bih, const float* __restrict__ bhh,
          float* __restrict__ dout)
{
    __shared__ float h_sh[NB * SSTR];
    __shared__ float x_sh[NB * SSTR];

    const int tid  = threadIdx.x;
    const int warp = tid >> 5;
    const int lane = tid & 31;
    const int gid  = lane >> 2;   // 0..7
    const int tig  = lane & 3;    // 0..3
    const int b0   = blockIdx.x * NB;

    // Warp tile: m-tile (16 rows) = warp&1, col group (16 cols) = warp>>1.
    const int mrow = (warp & 1) * 16;
    const int ncol = (warp >> 1) * 16;

    // ---- B-operand fragments (resident in registers all kernel) ----
    // D = A @ B with A[m][k] = h[b][k] (or x), B[k][n] = W[n][k] (W row-major [j][k]).
    // m16n8k8 B frag (col-major KxN): b0 = B(tig, gid), b1 = B(tig+4, gid).
    uint32_t whh[2][8][2], wih[2][8][2];
    #pragma unroll
    for (int nt = 0; nt < 2; ++nt) {
        const int n = ncol + nt * 8 + gid;
        #pragma unroll
        for (int kt = 0; kt < 8; ++kt) {
            const int k = kt * 8 + tig;
            whh[nt][kt][0] = f2tf(Whh[n * H + k]);
            whh[nt][kt][1] = f2tf(Whh[n * H + k + 4]);
            wih[nt][kt][0] = f2tf(Wih[n * IN + k]);
            wih[nt][kt][1] = f2tf(Wih[n * IN + k + 4]);
        }
    }

    // Folded bias per accumulator column (c0/c2 share col, c1/c3 share col+1).
    float bias[2][2];
    #pragma unroll
    for (int nt = 0; nt < 2; ++nt) {
        const int col = ncol + nt * 8 + 2 * tig;
        bias[nt][0] = bih[col]     + bhh[col];
        bias[nt][1] = bih[col + 1] + bhh[col + 1];
    }

    // ---- init h_sh from h0 (tf32-rounded; it is only ever an A operand) ----
    for (int idx = tid; idx < NB * H; idx += NTHREADS) {
        const int r = idx >> 6, c = idx & 63;
        ((uint32_t*)h_sh)[r * SSTR + c] = f2tf(h0[(b0 + r) * H + c]);
    }

    // ---- prefetch x for t = 0 ----
    const int xr0 = tid >> 4;         // 0..15 (and +16 for second half)
    const int xc0 = (tid & 15) * 4;   // float4 column
    float4 xa = *(const float4*)(x + ((size_t)(b0 + xr0)      * T + 0) * IN + xc0);
    float4 xb = *(const float4*)(x + ((size_t)(b0 + 16 + xr0) * T + 0) * IN + xc0);
    {
        uint4 ua = { f2tf(xa.x), f2tf(xa.y), f2tf(xa.z), f2tf(xa.w) };
        uint4 ub = { f2tf(xb.x), f2tf(xb.y), f2tf(xb.z), f2tf(xb.w) };
        *(uint4*)(&((uint32_t*)x_sh)[xr0 * SSTR + xc0])        = ua;
        *(uint4*)(&((uint32_t*)x_sh)[(16 + xr0) * SSTR + xc0]) = ub;
    }
    __syncthreads();

    const uint32_t* hsu = (const uint32_t*)h_sh;
    const uint32_t* xsu = (const uint32_t*)x_sh;

    float* __restrict__ outp = dout + Bsz * H;   // [hT | out] layout
    float hval[2][4];

    const int arow0 = (mrow + gid) * SSTR;
    const int arow1 = arow0 + 8 * SSTR;

    for (int t = 0; t < T; ++t) {
        // Prefetch next timestep's x into registers (hidden under compute).
        if (t + 1 < T) {
            xa = *(const float4*)(x + ((size_t)(b0 + xr0)      * T + (t + 1)) * IN + xc0);
            xb = *(const float4*)(x + ((size_t)(b0 + 16 + xr0) * T + (t + 1)) * IN + xc0);
        }

        float c[2][4] = {{0.f,0.f,0.f,0.f},{0.f,0.f,0.f,0.f}};
        uint32_t a[4];

        // x_t @ W_ih^T
        #pragma unroll
        for (int kt = 0; kt < 8; ++kt) {
            const int kc = kt * 8 + tig;
            a[0] = xsu[arow0 + kc];
            a[1] = xsu[arow1 + kc];
            a[2] = xsu[arow0 + kc + 4];
            a[3] = xsu[arow1 + kc + 4];
            mma8(c[0], a, wih[0][kt]);
            mma8(c[1], a, wih[1][kt]);
        }
        // h_{t-1} @ W_hh^T
        #pragma unroll
        for (int kt = 0; kt < 8; ++kt) {
            const int kc = kt * 8 + tig;
            a[0] = hsu[arow0 + kc];
            a[1] = hsu[arow1 + kc];
            a[2] = hsu[arow0 + kc + 4];
            a[3] = hsu[arow1 + kc + 4];
            mma8(c[0], a, whh[0][kt]);
            mma8(c[1], a, whh[1][kt]);
        }

        // epilogue: bias + tanh
        #pragma unroll
        for (int nt = 0; nt < 2; ++nt) {
            hval[nt][0] = fast_tanh(c[nt][0] + bias[nt][0]);
            hval[nt][1] = fast_tanh(c[nt][1] + bias[nt][1]);
            hval[nt][2] = fast_tanh(c[nt][2] + bias[nt][0]);
            hval[nt][3] = fast_tanh(c[nt][3] + bias[nt][1]);
        }

        // write out[b*T + t][:]
        const int row0 = b0 + mrow + gid;
        #pragma unroll
        for (int nt = 0; nt < 2; ++nt) {
            const int col = ncol + nt * 8 + 2 * tig;
            *(float2*)(outp + ((size_t)row0 * T + t) * H + col) =
                make_float2(hval[nt][0], hval[nt][1]);
            *(float2*)(outp + ((size_t)(row0 + 8) * T + t) * H + col) =
                make_float2(hval[nt][2], hval[nt][3]);
        }

        __syncthreads();  // everyone done reading h_sh / x_sh for step t

        // publish h_t (tf32-rounded) and x_{t+1}
        {
            uint32_t* hsw = (uint32_t*)h_sh;
            const int r0 = (mrow + gid) * SSTR;
            const int r1 = r0 + 8 * SSTR;
            #pragma unroll
            for (int nt = 0; nt < 2; ++nt) {
                const int col = ncol + nt * 8 + 2 * tig;
                hsw[r0 + col]     = f2tf(hval[nt][0]);
                hsw[r0 + col + 1] = f2tf(hval[nt][1]);
                hsw[r1 + col]     = f2tf(hval[nt][2]);
                hsw[r1 + col + 1] = f2tf(hval[nt][3]);
            }
            if (t + 1 < T) {
                uint32_t* xsw = (uint32_t*)x_sh;
                uint4 ua = { f2tf(xa.x), f2tf(xa.y), f2tf(xa.z), f2tf(xa.w) };
                uint4 ub = { f2tf(xb.x), f2tf(xb.y), f2tf(xb.z), f2tf(xb.w) };
                *(uint4*)(&xsw[xr0 * SSTR + xc0])        = ua;
                *(uint4*)(&xsw[(16 + xr0) * SSTR + xc0]) = ub;
            }
        }
        __syncthreads();
    }

    // final hidden state hT -> dout[0 : B*H)
    const int row0 = b0 + mrow + gid;
    #pragma unroll
    for (int nt = 0; nt < 2; ++nt) {
        const int col = ncol + nt * 8 + 2 * tig;
        *(float2*)(dout + (size_t)row0 * H + col) =
            make_float2(hval[nt][0], hval[nt][1]);
        *(float2*)(dout + (size_t)(row0 + 8) * H + col) =
            make_float2(hval[nt][2], hval[nt][3]);
    }
}

extern "C" void kernel_launch(void* const* d_in, const int* in_sizes, int n_in,
                              void* d_out, int out_size) {
    const float* x   = (const float*)d_in[0];
    const float* h0  = (const float*)d_in[1];
    const float* Wih = (const float*)d_in[2];
    const float* Whh = (const float*)d_in[3];
    const float* bih = (const float*)d_in[4];
    const float* bhh = (const float*)d_in[5];
    (void)in_sizes; (void)n_in; (void)out_size;

    rnn_fused<<<Bsz / NB, NTHREADS>>>(x, h0, Wih, Whh, bih, bhh, (float*)d_out);
}

// round 2
// speedup vs baseline: 1.0008x; 1.0008x over previous
#include <cuda_runtime.h>
#include <cstdint>

// Problem: vanilla tanh RNN
//   h_t = tanh(x_t W_ih^T + b_ih + h_{t-1} W_hh^T + b_hh)
//   outputs: (h_T [1,B,H], all h_t flattened [B*T, H])
// B=4096, T=256, I=H=64.
//
// Fused persistent kernel: 128 blocks x 256 threads, each block owns 32 batch
// rows for all 256 steps. Per step: two [32x64]@[64x64] tf32 warp-MMA GEMMs.
// Weights live in registers as B-fragments for the whole kernel; h lives in
// shared memory; x(t+1) is prefetched from gmem during step t.

constexpr int Bsz = 4096;
constexpr int T   = 256;
constexpr int IN  = 64;
constexpr int H   = 64;
constexpr int NB  = 32;    // batch rows per block
constexpr int SSTR = 68;   // padded shared row stride (conflict-free frag LDS)
constexpr int NTHREADS = 256;

__device__ __forceinline__ uint32_t f2tf(float f) {
    uint32_t r;
    asm("cvt.rna.tf32.f32 %0, %1;" : "=r"(r) : "f"(f));
    return r;
}

__device__ __forceinline__ void mma8(float* c, const uint32_t* a, const uint32_t* b) {
    asm volatile(
        "mma.sync.aligned.m16n8k8.row.col.f32.tf32.tf32.f32 "
        "{%0,%1,%2,%3}, {%4,%5,%6,%7}, {%8,%9}, {%0,%1,%2,%3};"
        : "+f"(c[0]), "+f"(c[1]), "+f"(c[2]), "+f"(c[3])
        : "r"(a[0]), "r"(a[1]), "r"(a[2]), "r"(a[3]), "r"(b[0]), "r"(b[1]));
}

// Accurate-enough fast tanh: 1 - 2/(e^{2z}+1).
// __expf -> MUFU.EX2 (rel err ~2^-21); __fdividef(2, huge) -> 0 so saturation
// at +/-1 is exact. Near z=0 the cancellation is benign (abs err ~ulp(1)).
__device__ __forceinline__ float fast_tanh(float z) {
    float e = __expf(2.0f * z);
    return 1.0f - __fdividef(2.0f, e + 1.0f);
}

__global__ void __launch_bounds__(NTHREADS, 1)
rnn_fused(const float* __restrict__ x, const float* __restrict__ h0,
          const float* __restrict__ Wih, const float* __restrict__ Whh,
          const float* __restrict__ bih, const float* __restrict__ bhh,
          float* __restrict__ dout)
{
    __shared__ float h_sh[NB * SSTR];
    __shared__ float x_sh[NB * SSTR];

    const int tid  = threadIdx.x;
    const int warp = tid >> 5;
    const int lane = tid & 31;
    const int gid  = lane >> 2;   // 0..7
    const int tig  = lane & 3;    // 0..3
    const int b0   = blockIdx.x * NB;

    // Warp tile: m-tile (16 rows) = warp&1, col group (16 cols) = warp>>1.
    const int mrow = (warp & 1) * 16;
    const int ncol = (warp >> 1) * 16;

    // ---- B-operand fragments (resident in registers all kernel) ----
    // D = A @ B with A[m][k] = h[b][k] (or x), B[k][n] = W[n][k] (W row-major [j][k]).
    // m16n8k8 B frag (col-major KxN): b0 = B(tig, gid), b1 = B(tig+4, gid).
    uint32_t whh[2][8][2], wih[2][8][2];
    #pragma unroll
    for (int nt = 0; nt < 2; ++nt) {
        const int n = ncol + nt * 8 + gid;
        #pragma unroll
        for (int kt = 0; kt < 8; ++kt) {
            const int k = kt * 8 + tig;
            whh[nt][kt][0] = f2tf(Whh[n * H + k]);
            whh[nt][kt][1] = f2tf(Whh[n * H + k + 4]);
            wih[nt][kt][0] = f2tf(Wih[n * IN + k]);
            wih[nt][kt][1] = f2tf(Wih[n * IN + k + 4]);
        }
    }

    // Folded bias per accumulator column (c0/c2 share col, c1/c3 share col+1).
    float bias[2][2];
    #pragma unroll
    for (int nt = 0; nt < 2; ++nt) {
        const int col = ncol + nt * 8 + 2 * tig;
        bias[nt][0] = bih[col]     + bhh[col];
        bias[nt][1] = bih[col + 1] + bhh[col + 1];
    }

    // ---- init h_sh from h0 (tf32-rounded; it is only ever an A operand) ----
    for (int idx = tid; idx < NB * H; idx += NTHREADS) {
        const int r = idx >> 6, c = idx & 63;
        ((uint32_t*)h_sh)[r * SSTR + c] = f2tf(h0[(b0 + r) * H + c]);
    }

    // ---- prefetch x for t = 0 ----
    const int xr0 = tid >> 4;         // 0..15 (and +16 for second half)
    const int xc0 = (tid & 15) * 4;   // float4 column
    float4 xa = *(const float4*)(x + ((size_t)(b0 + xr0)      * T + 0) * IN + xc0);
    float4 xb = *(const float4*)(x + ((size_t)(b0 + 16 + xr0) * T + 0) * IN + xc0);
    {
        uint4 ua = { f2tf(xa.x), f2tf(xa.y), f2tf(xa.z), f2tf(xa.w) };
        uint4 ub = { f2tf(xb.x), f2tf(xb.y), f2tf(xb.z), f2tf(xb.w) };
        *(uint4*)(&((uint32_t*)x_sh)[xr0 * SSTR + xc0])        = ua;
        *(uint4*)(&((uint32_t*)x_sh)[(16 + xr0) * SSTR + xc0]) = ub;
    }
    __syncthreads();

    const uint32_t* hsu = (const uint32_t*)h_sh;
    const uint32_t* xsu = (const uint32_t*)x_sh;

    float* __restrict__ outp = dout + Bsz * H;   // [hT | out] layout
    float hval[2][4];

    const int arow0 = (mrow + gid) * SSTR;
    const int arow1 = arow0 + 8 * SSTR;

    for (int t = 0; t < T; ++t) {
        // Prefetch next timestep's x into registers (hidden under compute).
        if (t + 1 < T) {
            xa = *(const float4*)(x + ((size_t)(b0 + xr0)      * T + (t + 1)) * IN + xc0);
            xb = *(const float4*)(x + ((size_t)(b0 + 16 + xr0) * T + (t + 1)) * IN + xc0);
        }

        float c[2][4] = {{0.f,0.f,0.f,0.f},{0.f,0.f,0.f,0.f}};
        uint32_t a[4];

        // x_t @ W_ih^T
        #pragma unroll
        for (int kt = 0; kt < 8; ++kt) {
            const int kc = kt * 8 + tig;
            a[0] = xsu[arow0 + kc];
            a[1] = xsu[arow1 + kc];
            a[2] = xsu[arow0 + kc + 4];
            a[3] = xsu[arow1 + kc + 4];
            mma8(c[0], a, wih[0][kt]);
            mma8(c[1], a, wih[1][kt]);
        }
        // h_{t-1} @ W_hh^T
        #pragma unroll
        for (int kt = 0; kt < 8; ++kt) {
            const int kc = kt * 8 + tig;
            a[0] = hsu[arow0 + kc];
            a[1] = hsu[arow1 + kc];
            a[2] = hsu[arow0 + kc + 4];
            a[3] = hsu[arow1 + kc + 4];
            mma8(c[0], a, whh[0][kt]);
            mma8(c[1], a, whh[1][kt]);
        }

        // epilogue: bias + tanh
        #pragma unroll
        for (int nt = 0; nt < 2; ++nt) {
            hval[nt][0] = fast_tanh(c[nt][0] + bias[nt][0]);
            hval[nt][1] = fast_tanh(c[nt][1] + bias[nt][1]);
            hval[nt][2] = fast_tanh(c[nt][2] + bias[nt][0]);
            hval[nt][3] = fast_tanh(c[nt][3] + bias[nt][1]);
        }

        // write out[b*T + t][:]
        const int row0 = b0 + mrow + gid;
        #pragma unroll
        for (int nt = 0; nt < 2; ++nt) {
            const int col = ncol + nt * 8 + 2 * tig;
            *(float2*)(outp + ((size_t)row0 * T + t) * H + col) =
                make_float2(hval[nt][0], hval[nt][1]);
            *(float2*)(outp + ((size_t)(row0 + 8) * T + t) * H + col) =
                make_float2(hval[nt][2], hval[nt][3]);
        }

        __syncthreads();  // everyone done reading h_sh / x_sh for step t

        // publish h_t (tf32-rounded) and x_{t+1}
        {
            uint32_t* hsw = (uint32_t*)h_sh;
            const int r0 = (mrow + gid) * SSTR;
            const int r1 = r0 + 8 * SSTR;
            #pragma unroll
            for (int nt = 0; nt < 2; ++nt) {
                const int col = ncol + nt * 8 + 2 * tig;
                hsw[r0 + col]     = f2tf(hval[nt][0]);
                hsw[r0 + col + 1] = f2tf(hval[nt][1]);
                hsw[r1 + col]     = f2tf(hval[nt][2]);
                hsw[r1 + col + 1] = f2tf(hval[nt][3]);
            }
            if (t + 1 < T) {
                uint32_t* xsw = (uint32_t*)x_sh;
                uint4 ua = { f2tf(xa.x), f2tf(xa.y), f2tf(xa.z), f2tf(xa.w) };
                uint4 ub = { f2tf(xb.x), f2tf(xb.y), f2tf(xb.z), f2tf(xb.w) };
                *(uint4*)(&xsw[xr0 * SSTR + xc0])        = ua;
                *(uint4*)(&xsw[(16 + xr0) * SSTR + xc0]) = ub;
            }
        }
        __syncthreads();
    }

    // final hidden state hT -> dout[0 : B*H)
    const int row0 = b0 + mrow + gid;
    #pragma unroll
    for (int nt = 0; nt < 2; ++nt) {
        const int col = ncol + nt * 8 + 2 * tig;
        *(float2*)(dout + (size_t)row0 * H + col) =
            make_float2(hval[nt][0], hval[nt][1]);
        *(float2*)(dout + (size_t)(row0 + 8) * H + col) =
            make_float2(hval[nt][2], hval[nt][3]);
    }
}

extern "C" void kernel_launch(void* const* d_in, const int* in_sizes, int n_in,
                              void* d_out, int out_size) {
    const float* x   = (const float*)d_in[0];
    const float* h0  = (const float*)d_in[1];
    const float* Wih = (const float*)d_in[2];
    const float* Whh = (const float*)d_in[3];
    const float* bih = (const float*)d_in[4];
    const float* bhh = (const float*)d_in[5];
    (void)in_sizes; (void)n_in; (void)out_size;

    rnn_fused<<<Bsz / NB, NTHREADS>>>(x, h0, Wih, Whh, bih, bhh, (float*)d_out);
}

// round 3
// speedup vs baseline: 1.2238x; 1.2228x over previous
#include <cuda_runtime.h>
#include <cuda_fp16.h>
#include <cstdint>

// Vanilla tanh RNN: h_t = tanh(x_t W_ih^T + b_ih + h_{t-1} W_hh^T + b_hh)
// B=4096, T=256, I=H=64. Outputs: [hT (B*H) | all h_t (B*T*H)].
//
// Fused persistent kernel, 128 blocks x 256 threads, 32 batch rows/block.
// fp16 m16n8k16 MMA (fp32 accum). Weights live in registers (B-fragments).
// h double-buffered in smem (half2), ONE barrier/step. x-projection for step
// t+1 computed during step t into separate accumulators (bias pre-folded),
// so the recurrence chain is only the 4-MMA h-GEMM. x prefetched gmem->regs
// with 2-step pipeline, regs->smem as half2.

constexpr int Bsz = 4096;
constexpr int T   = 256;
constexpr int H   = 64;
constexpr int NB  = 32;    // batch rows per block
constexpr int SU  = 36;    // smem row stride in u32 (half2) units, conflict-free
constexpr int NTHREADS = 256;

__device__ __forceinline__ uint32_t packh2(float a, float b) {
    __half2 h = __floats2half2_rn(a, b);
    return *reinterpret_cast<uint32_t*>(&h);
}

__device__ __forceinline__ void mma16(float* c, const uint32_t* a, const uint32_t* b) {
    asm volatile(
        "mma.sync.aligned.m16n8k16.row.col.f32.f16.f16.f32 "
        "{%0,%1,%2,%3}, {%4,%5,%6,%7}, {%8,%9}, {%0,%1,%2,%3};"
        : "+f"(c[0]), "+f"(c[1]), "+f"(c[2]), "+f"(c[3])
        : "r"(a[0]), "r"(a[1]), "r"(a[2]), "r"(a[3]), "r"(b[0]), "r"(b[1]));
}

// tanh = 1 - 2/(e^{2z}+1); EX2 + RCP, saturates exactly at +/-1.
__device__ __forceinline__ float fast_tanh(float z) {
    float e = __expf(2.0f * z);
    return 1.0f - __fdividef(2.0f, e + 1.0f);
}

__global__ void __launch_bounds__(NTHREADS, 1)
rnn_fused(const float* __restrict__ x, const float* __restrict__ h0,
          const float* __restrict__ Wih, const float* __restrict__ Whh,
          const float* __restrict__ bih, const float* __restrict__ bhh,
          float* __restrict__ dout)
{
    __shared__ uint32_t hbuf[2][NB * SU];   // h_{t} as half2, ping-pong
    __shared__ uint32_t xbuf[2][NB * SU];   // x_t as half2, ping-pong

    const int tid  = threadIdx.x;
    const int warp = tid >> 5;
    const int lane = tid & 31;
    const int gid  = lane >> 2;   // 0..7
    const int tig  = lane & 3;    // 0..3
    const int b0   = blockIdx.x * NB;

    const int mrow = (warp & 1) * 16;   // 16-row m-tile
    const int ncol = (warp >> 1) * 16;  // 16-col n-group (2 x n8)

    // ---- weight B-fragments (fp16, resident all kernel) ----
    // D = A @ B, B[k][n] = W[n][k]. m16n8k16 B frag:
    //   b0 = {W[n][k+2tig], W[n][k+2tig+1]}, b1 = same at k+8.
    uint32_t wih[2][4][2], whh[2][4][2];
    #pragma unroll
    for (int nt = 0; nt < 2; ++nt) {
        const int n = ncol + nt * 8 + gid;
        #pragma unroll
        for (int kt = 0; kt < 4; ++kt) {
            const int k = kt * 16 + 2 * tig;
            wih[nt][kt][0] = packh2(Wih[n * H + k],     Wih[n * H + k + 1]);
            wih[nt][kt][1] = packh2(Wih[n * H + k + 8], Wih[n * H + k + 9]);
            whh[nt][kt][0] = packh2(Whh[n * H + k],     Whh[n * H + k + 1]);
            whh[nt][kt][1] = packh2(Whh[n * H + k + 8], Whh[n * H + k + 9]);
        }
    }

    // combined bias per accumulator column
    float bias[2][2];
    #pragma unroll
    for (int nt = 0; nt < 2; ++nt) {
        const int col = ncol + nt * 8 + 2 * tig;
        bias[nt][0] = bih[col]     + bhh[col];
        bias[nt][1] = bih[col + 1] + bhh[col + 1];
    }

    // ---- init h0 into hbuf[0] (half2) ----
    for (int idx = tid; idx < NB * 32; idx += NTHREADS) {
        const int r = idx >> 5, c = idx & 31;
        hbuf[0][r * SU + c] =
            packh2(h0[(b0 + r) * H + 2 * c], h0[(b0 + r) * H + 2 * c + 1]);
    }

    // ---- x loaders: each thread covers rows xr0 and xr0+16, 4 float cols ----
    const int xr0 = tid >> 4;          // 0..15
    const int xcf = (tid & 15) * 4;    // float column
    const int xcu = (tid & 15) * 2;    // u32 (half2) column

    // x(0) straight into xbuf[0]
    {
        float4 va = *(const float4*)(x + ((size_t)(b0 + xr0)      * T + 0) * H + xcf);
        float4 vb = *(const float4*)(x + ((size_t)(b0 + 16 + xr0) * T + 0) * H + xcf);
        *(uint2*)&xbuf[0][xr0 * SU + xcu]        = make_uint2(packh2(va.x, va.y), packh2(va.z, va.w));
        *(uint2*)&xbuf[0][(16 + xr0) * SU + xcu] = make_uint2(packh2(vb.x, vb.y), packh2(vb.z, vb.w));
    }
    __syncthreads();

    const int ar0 = (mrow + gid) * SU;
    const int ar1 = ar0 + 8 * SU;

    // ---- acc = bias + x(0) @ W_ih^T ----
    float acc[2][4] = {{bias[0][0], bias[0][1], bias[0][0], bias[0][1]},
                       {bias[1][0], bias[1][1], bias[1][0], bias[1][1]}};
    #pragma unroll
    for (int kt = 0; kt < 4; ++kt) {
        uint32_t a[4];
        const int o = kt * 8 + tig;
        a[0] = xbuf[0][ar0 + o];     a[1] = xbuf[0][ar1 + o];
        a[2] = xbuf[0][ar0 + o + 4]; a[3] = xbuf[0][ar1 + o + 4];
        mma16(acc[0], a, wih[0][kt]);
        mma16(acc[1], a, wih[1][kt]);
    }

    // x(1) -> xbuf[1]; prefetch x(2), x(3) into register pipeline
    {
        float4 va = *(const float4*)(x + ((size_t)(b0 + xr0)      * T + 1) * H + xcf);
        float4 vb = *(const float4*)(x + ((size_t)(b0 + 16 + xr0) * T + 1) * H + xcf);
        *(uint2*)&xbuf[1][xr0 * SU + xcu]        = make_uint2(packh2(va.x, va.y), packh2(va.z, va.w));
        *(uint2*)&xbuf[1][(16 + xr0) * SU + xcu] = make_uint2(packh2(vb.x, vb.y), packh2(vb.z, vb.w));
    }
    float4 xra[2], xrb[2];
    xra[0] = *(const float4*)(x + ((size_t)(b0 + xr0)      * T + 2) * H + xcf);
    xrb[0] = *(const float4*)(x + ((size_t)(b0 + 16 + xr0) * T + 2) * H + xcf);
    xra[1] = *(const float4*)(x + ((size_t)(b0 + xr0)      * T + 3) * H + xcf);
    xrb[1] = *(const float4*)(x + ((size_t)(b0 + 16 + xr0) * T + 3) * H + xcf);
    __syncthreads();

    float* __restrict__ outp = dout + (size_t)Bsz * H;   // [hT | out]
    float hval[2][4];
    const int row0 = b0 + mrow + gid;

    #pragma unroll 2
    for (int t = 0; t < T; ++t) {
        const int p = t & 1;

        // ---- recurrence GEMM: acc += h_{t-1} @ W_hh^T (4-deep chain) ----
        {
            const uint32_t* hs = hbuf[p];
            #pragma unroll
            for (int kt = 0; kt < 4; ++kt) {
                uint32_t a[4];
                const int o = kt * 8 + tig;
                a[0] = hs[ar0 + o];     a[1] = hs[ar1 + o];
                a[2] = hs[ar0 + o + 4]; a[3] = hs[ar1 + o + 4];
                mma16(acc[0], a, whh[0][kt]);
                mma16(acc[1], a, whh[1][kt]);
            }
        }

        // ---- independent: cxn = bias + x(t+1) @ W_ih^T ----
        float cxn[2][4] = {{bias[0][0], bias[0][1], bias[0][0], bias[0][1]},
                           {bias[1][0], bias[1][1], bias[1][0], bias[1][1]}};
        if (t + 1 < T) {
            const uint32_t* xs = xbuf[p ^ 1];
            #pragma unroll
            for (int kt = 0; kt < 4; ++kt) {
                uint32_t a[4];
                const int o = kt * 8 + tig;
                a[0] = xs[ar0 + o];     a[1] = xs[ar1 + o];
                a[2] = xs[ar0 + o + 4]; a[3] = xs[ar1 + o + 4];
                mma16(cxn[0], a, wih[0][kt]);
                mma16(cxn[1], a, wih[1][kt]);
            }
        }

        // ---- activation ----
        #pragma unroll
        for (int nt = 0; nt < 2; ++nt) {
            hval[nt][0] = fast_tanh(acc[nt][0]);
            hval[nt][1] = fast_tanh(acc[nt][1]);
            hval[nt][2] = fast_tanh(acc[nt][2]);
            hval[nt][3] = fast_tanh(acc[nt][3]);
        }

        // ---- store out[b*T+t][:] (fp32) ----
        #pragma unroll
        for (int nt = 0; nt < 2; ++nt) {
            const int col = ncol + nt * 8 + 2 * tig;
            *(float2*)(outp + ((size_t)row0 * T + t) * H + col) =
                make_float2(hval[nt][0], hval[nt][1]);
            *(float2*)(outp + ((size_t)(row0 + 8) * T + t) * H + col) =
                make_float2(hval[nt][2], hval[nt][3]);
        }

        // ---- publish h_t (half2) into the other buffer ----
        {
            uint32_t* hw = hbuf[p ^ 1];
            #pragma unroll
            for (int nt = 0; nt < 2; ++nt) {
                const int cu = (ncol >> 1) + nt * 4 + tig;
                hw[ar0 + cu] = packh2(hval[nt][0], hval[nt][1]);
                hw[ar1 + cu] = packh2(hval[nt][2], hval[nt][3]);
            }
        }

        // ---- x pipeline: store x(t+2) (loaded 2 steps ago), fetch x(t+4) ----
        if (t + 2 < T) {
            uint32_t* xw = xbuf[p];
            *(uint2*)&xw[xr0 * SU + xcu] =
                make_uint2(packh2(xra[p].x, xra[p].y), packh2(xra[p].z, xra[p].w));
            *(uint2*)&xw[(16 + xr0) * SU + xcu] =
                make_uint2(packh2(xrb[p].x, xrb[p].y), packh2(xrb[p].z, xrb[p].w));
        }
        if (t + 4 < T) {
            xra[p] = *(const float4*)(x + ((size_t)(b0 + xr0)      * T + (t + 4)) * H + xcf);
            xrb[p] = *(const float4*)(x + ((size_t)(b0 + 16 + xr0) * T + (t + 4)) * H + xcf);
        }

        // rotate accumulators
        #pragma unroll
        for (int nt = 0; nt < 2; ++nt)
            #pragma unroll
            for (int i = 0; i < 4; ++i)
                acc[nt][i] = cxn[nt][i];

        __syncthreads();
    }

    // ---- final hidden state hT ----
    #pragma unroll
    for (int nt = 0; nt < 2; ++nt) {
        const int col = ncol + nt * 8 + 2 * tig;
        *(float2*)(dout + (size_t)row0 * H + col) =
            make_float2(hval[nt][0], hval[nt][1]);
        *(float2*)(dout + (size_t)(row0 + 8) * H + col) =
            make_float2(hval[nt][2], hval[nt][3]);
    }
}

extern "C" void kernel_launch(void* const* d_in, const int* in_sizes, int n_in,
                              void* d_out, int out_size) {
    const float* x   = (const float*)d_in[0];
    const float* h0  = (const float*)d_in[1];
    const float* Wih = (const float*)d_in[2];
    const float* Whh = (const float*)d_in[3];
    const float* bih = (const float*)d_in[4];
    const float* bhh = (const float*)d_in[5];
    (void)in_sizes; (void)n_in; (void)out_size;

    rnn_fused<<<Bsz / NB, NTHREADS>>>(x, h0, Wih, Whh, bih, bhh, (float*)d_out);
}

// round 4
// speedup vs baseline: 1.2644x; 1.0332x over previous
#include <cuda_runtime.h>
#include <cuda_fp16.h>
#include <cstdint>

// Vanilla tanh RNN: h_t = tanh(x_t W_ih^T + b_ih + h_{t-1} W_hh^T + b_hh)
// B=4096, T=256, I=H=64. Output: [hT (B*H) | all h_t (B*T*H)].
//
// 128 blocks x 256 threads, 32 batch rows/block, fp16 m16n8k16 MMA (fp32 acc).
// Weights register-resident. h/x double-buffered in smem (half2), A-fragments
// via ldmatrix.x4. Per step ONE named barrier per independent half-block
// (rows 0-15 / 16-31 never interact). All non-critical work (out stores,
// x-projection of t+1, x prefetch pipeline) happens after the barrier.

constexpr int Bsz = 4096;
constexpr int T   = 256;
constexpr int H   = 64;
constexpr int NB  = 32;    // batch rows per block
constexpr int SU  = 36;    // smem row stride in u32 (half2) units
constexpr int NTHREADS = 256;

__device__ __forceinline__ uint32_t packh2(float a, float b) {
    __half2 h = __floats2half2_rn(a, b);
    return *reinterpret_cast<uint32_t*>(&h);
}

__device__ __forceinline__ void mma16(float* c, const uint32_t* a, const uint32_t* b) {
    asm volatile(
        "mma.sync.aligned.m16n8k16.row.col.f32.f16.f16.f32 "
        "{%0,%1,%2,%3}, {%4,%5,%6,%7}, {%8,%9}, {%0,%1,%2,%3};"
        : "+f"(c[0]), "+f"(c[1]), "+f"(c[2]), "+f"(c[3])
        : "r"(a[0]), "r"(a[1]), "r"(a[2]), "r"(a[3]), "r"(b[0]), "r"(b[1]));
}

__device__ __forceinline__ void ldsm4(uint32_t* a, uint32_t addr) {
    asm volatile("ldmatrix.sync.aligned.m8n8.x4.shared.b16 {%0,%1,%2,%3}, [%4];"
                 : "=r"(a[0]), "=r"(a[1]), "=r"(a[2]), "=r"(a[3])
                 : "r"(addr));
}

// tanh = 1 - 2/(e^{2z}+1); EX2+RCP, exact saturation at +/-1.
__device__ __forceinline__ float fast_tanh(float z) {
    float e = __expf(2.0f * z);
    return 1.0f - __fdividef(2.0f, e + 1.0f);
}

// one GEMM over K=64: 4 k-tiles, A from smem via ldmatrix, B (weights) in regs
#define GEMM4(ACC, W, BASE)                                            \
    {                                                                  \
        _Pragma("unroll")                                              \
        for (int kt_ = 0; kt_ < 4; ++kt_) {                            \
            uint32_t a_[4];                                            \
            ldsm4(a_, (BASE) + kt_ * 32);                              \
            mma16((ACC)[0], a_, (W)[0][kt_]);                          \
            mma16((ACC)[1], a_, (W)[1][kt_]);                          \
        }                                                              \
    }

#define STEP(t, ACC, NXT)                                              \
    {                                                                  \
        const int p_ = (t) & 1;                                        \
        /* critical: recurrence GEMM + activation + publish */         \
        GEMM4(ACC, whh, hb[p_] + aoff);                                \
        _Pragma("unroll")                                              \
        for (int nt = 0; nt < 2; ++nt) {                               \
            hval[nt][0] = fast_tanh((ACC)[nt][0]);                     \
            hval[nt][1] = fast_tanh((ACC)[nt][1]);                     \
            hval[nt][2] = fast_tanh((ACC)[nt][2]);                     \
            hval[nt][3] = fast_tanh((ACC)[nt][3]);                     \
        }                                                              \
        {                                                              \
            uint32_t* hw_ = hbuf[p_ ^ 1];                              \
            _Pragma("unroll")                                          \
            for (int nt = 0; nt < 2; ++nt) {                           \
                const int cu_ = (ncol >> 1) + nt * 4 + tig;            \
                hw_[ar0 + cu_] = packh2(hval[nt][0], hval[nt][1]);     \
                hw_[ar1 + cu_] = packh2(hval[nt][2], hval[nt][3]);     \
            }                                                          \
        }                                                              \
        asm volatile("bar.sync %0, 128;" :: "r"(1 + g) : "memory");    \
        /* tail (overlaps next step's chain): out stores */            \
        _Pragma("unroll")                                              \
        for (int nt = 0; nt < 2; ++nt) {                               \
            const int col_ = ncol + nt * 8 + 2 * tig;                  \
            *(float2*)(outp + ((size_t)row0 * T + (t)) * H + col_) =   \
                make_float2(hval[nt][0], hval[nt][1]);                 \
            *(float2*)(outp + ((size_t)(row0 + 8) * T + (t)) * H + col_) = \
                make_float2(hval[nt][2], hval[nt][3]);                 \
        }                                                              \
        /* x pipeline: push x(t+2) to smem, fetch x(t+4) to regs */    \
        if ((t) + 2 < T) {                                             \
            uint32_t* xw_ = xbuf[p_];                                  \
            float4 va_ = xr[(t) & 1][0], vb_ = xr[(t) & 1][1];         \
            *(uint4*)&xw_[xsrow * SU + xcu] = make_uint4(              \
                packh2(va_.x, va_.y), packh2(va_.z, va_.w),            \
                packh2(vb_.x, vb_.y), packh2(vb_.z, vb_.w));           \
        }                                                              \
        if ((t) + 4 < T) {                                             \
            xr[(t) & 1][0] = *(const float4*)(xg + ((t) + 4) * H);     \
            xr[(t) & 1][1] = *(const float4*)(xg + ((t) + 4) * H + 4); \
        }                                                              \
        /* x-projection for t+1 into the other acc bank */             \
        if ((t) + 1 < T) {                                             \
            _Pragma("unroll")                                          \
            for (int nt = 0; nt < 2; ++nt) {                           \
                (NXT)[nt][0] = bias[nt][0]; (NXT)[nt][1] = bias[nt][1];\
                (NXT)[nt][2] = bias[nt][0]; (NXT)[nt][3] = bias[nt][1];\
            }                                                          \
            GEMM4(NXT, wih, xb[p_ ^ 1] + aoff);                        \
        }                                                              \
    }

__global__ void __launch_bounds__(NTHREADS, 1)
rnn_fused(const float* __restrict__ x, const float* __restrict__ h0,
          const float* __restrict__ Wih, const float* __restrict__ Whh,
          const float* __restrict__ bih, const float* __restrict__ bhh,
          float* __restrict__ dout)
{
    __shared__ __align__(16) uint32_t hbuf[2][NB * SU];
    __shared__ __align__(16) uint32_t xbuf[2][NB * SU];

    const int tid  = threadIdx.x;
    const int warp = tid >> 5;
    const int lane = tid & 31;
    const int gid  = lane >> 2;
    const int tig  = lane & 3;
    const int b0   = blockIdx.x * NB;

    const int g    = warp & 1;          // half-block group (rows g*16..g*16+15)
    const int mrow = g * 16;
    const int ncol = (warp >> 1) * 16;  // 16-col n-group

    // ---- weight B-fragments (fp16, register resident) ----
    uint32_t wih[2][4][2], whh[2][4][2];
    #pragma unroll
    for (int nt = 0; nt < 2; ++nt) {
        const int n = ncol + nt * 8 + gid;
        #pragma unroll
        for (int kt = 0; kt < 4; ++kt) {
            const int k = kt * 16 + 2 * tig;
            wih[nt][kt][0] = packh2(Wih[n * H + k],     Wih[n * H + k + 1]);
            wih[nt][kt][1] = packh2(Wih[n * H + k + 8], Wih[n * H + k + 9]);
            whh[nt][kt][0] = packh2(Whh[n * H + k],     Whh[n * H + k + 1]);
            whh[nt][kt][1] = packh2(Whh[n * H + k + 8], Whh[n * H + k + 9]);
        }
    }

    float bias[2][2];
    #pragma unroll
    for (int nt = 0; nt < 2; ++nt) {
        const int col = ncol + nt * 8 + 2 * tig;
        bias[nt][0] = bih[col]     + bhh[col];
        bias[nt][1] = bih[col + 1] + bhh[col + 1];
    }

    // ---- smem byte bases + ldmatrix lane offset ----
    uint32_t hb[2], xb[2];
    hb[0] = (uint32_t)__cvta_generic_to_shared(&hbuf[0][0]);
    hb[1] = (uint32_t)__cvta_generic_to_shared(&hbuf[1][0]);
    xb[0] = (uint32_t)__cvta_generic_to_shared(&xbuf[0][0]);
    xb[1] = (uint32_t)__cvta_generic_to_shared(&xbuf[1][0]);
    // x4 matrices: m0=[r0-7,k0-7] m1=[r8-15,k0-7] m2=[r0-7,k8-15] m3=[r8-15,k8-15]
    {
    }
    const int mat = lane >> 3, mr = lane & 7;
    const uint32_t aoff =
        ((uint32_t)(mrow + (mat & 1) * 8 + mr) * SU + (uint32_t)(mat >> 1) * 4) * 4;

    // h-publish indices (u32 units)
    const int ar0 = (mrow + gid) * SU;
    const int ar1 = ar0 + 8 * SU;

    // ---- group-local x/h loader mapping: 128 threads cover 16 rows x 32 u32 ----
    const int lid   = (warp >> 1) * 32 + lane;   // 0..127 within group
    const int xsrow = mrow + (lid >> 3);         // block-local row
    const int xcu   = (lid & 7) * 4;             // u32 column (16B granule)
    const float* xg = x + (size_t)(b0 + xsrow) * T * H + xcu * 2;

    // h0 -> hbuf[0]
    {
        const float* hp = h0 + (size_t)(b0 + xsrow) * H + xcu * 2;
        float4 va = *(const float4*)(hp);
        float4 vb = *(const float4*)(hp + 4);
        *(uint4*)&hbuf[0][xsrow * SU + xcu] = make_uint4(
            packh2(va.x, va.y), packh2(va.z, va.w),
            packh2(vb.x, vb.y), packh2(vb.z, vb.w));
    }
    // x(0) -> xbuf[0], x(1) -> xbuf[1]
    #pragma unroll
    for (int tt = 0; tt < 2; ++tt) {
        float4 va = *(const float4*)(xg + tt * H);
        float4 vb = *(const float4*)(xg + tt * H + 4);
        *(uint4*)&xbuf[tt][xsrow * SU + xcu] = make_uint4(
            packh2(va.x, va.y), packh2(va.z, va.w),
            packh2(vb.x, vb.y), packh2(vb.z, vb.w));
    }
    // register pipeline: x(2) -> bank0, x(3) -> bank1
    float4 xr[2][2];
    xr[0][0] = *(const float4*)(xg + 2 * H);
    xr[0][1] = *(const float4*)(xg + 2 * H + 4);
    xr[1][0] = *(const float4*)(xg + 3 * H);
    xr[1][1] = *(const float4*)(xg + 3 * H + 4);

    __syncthreads();

    // ---- accA = bias + x(0) @ W_ih^T ----
    float accA[2][4], accB[2][4];
    #pragma unroll
    for (int nt = 0; nt < 2; ++nt) {
        accA[nt][0] = bias[nt][0]; accA[nt][1] = bias[nt][1];
        accA[nt][2] = bias[nt][0]; accA[nt][3] = bias[nt][1];
    }
    GEMM4(accA, wih, xb[0] + aoff);

    float* __restrict__ outp = dout + (size_t)Bsz * H;   // [hT | out]
    float hval[2][4];
    const int row0 = b0 + mrow + gid;

    for (int tt = 0; tt < T; tt += 2) {
        STEP(tt,     accA, accB);
        STEP(tt + 1, accB, accA);
    }

    // ---- final hidden state hT ----
    #pragma unroll
    for (int nt = 0; nt < 2; ++nt) {
        const int col = ncol + nt * 8 + 2 * tig;
        *(float2*)(dout + (size_t)row0 * H + col) =
            make_float2(hval[nt][0], hval[nt][1]);
        *(float2*)(dout + (size_t)(row0 + 8) * H + col) =
            make_float2(hval[nt][2], hval[nt][3]);
    }
}

extern "C" void kernel_launch(void* const* d_in, const int* in_sizes, int n_in,
                              void* d_out, int out_size) {
    const float* x   = (const float*)d_in[0];
    const float* h0  = (const float*)d_in[1];
    const float* Wih = (const float*)d_in[2];
    const float* Whh = (const float*)d_in[3];
    const float* bih = (const float*)d_in[4];
    const float* bhh = (const float*)d_in[5];
    (void)in_sizes; (void)n_in; (void)out_size;

    rnn_fused<<<Bsz / NB, NTHREADS>>>(x, h0, Wih, Whh, bih, bhh, (float*)d_out);
}